// round 1
// baseline (speedup 1.0000x reference)
#include <cuda_runtime.h>
#include <cuda_bf16.h>
#include <cstdint>

// Problem constants
#define S_LEN 2048
#define BATCH 2
#define EMBED 1024
#define HEADS 16
#define HDIM  64
#define M_ROWS (S_LEN * BATCH)      // 4096
#define QKV_COLS (3 * EMBED)        // 3072
#define ROW_STRIDE (BATCH * QKV_COLS) // 6144 floats per seq step in qkv

// Scratch (device globals; no allocation in kernel_launch)
__device__ float g_qkv[(size_t)M_ROWS * QKV_COLS];   // [S*B, 3E]
__device__ float g_attn[(size_t)M_ROWS * EMBED];     // [S*B, E]

// ---------------------------------------------------------------------------
// SGEMM: C[M,N] = A[M,K] * W[N,K]^T + bias[N]
// Block tile 128x128, K-step 8, 256 threads, 8x8 per thread.
// Requires M%128==0, N%128==0, K%8==0 (true here).
// ---------------------------------------------------------------------------
__global__ __launch_bounds__(256) void sgemm_bias_kernel(
    const float* __restrict__ A, const float* __restrict__ W,
    const float* __restrict__ bias, float* __restrict__ C,
    int M, int N, int K)
{
    __shared__ float As[8][128];
    __shared__ float Bs[8][128];

    const int tid = threadIdx.x;
    const int tx = tid & 15;
    const int ty = tid >> 4;
    const int rowBase = blockIdx.y * 128;
    const int colBase = blockIdx.x * 128;

    const int loadRow = tid >> 1;        // 0..127
    const int loadCol = (tid & 1) * 4;   // 0 or 4

    const float* Aptr = A + (size_t)(rowBase + loadRow) * K + loadCol;
    const float* Wptr = W + (size_t)(colBase + loadRow) * K + loadCol;

    float acc[8][8];
#pragma unroll
    for (int i = 0; i < 8; i++)
#pragma unroll
        for (int j = 0; j < 8; j++) acc[i][j] = 0.f;

    for (int k0 = 0; k0 < K; k0 += 8) {
        float4 av = *(const float4*)(Aptr + k0);
        float4 wv = *(const float4*)(Wptr + k0);
        As[loadCol + 0][loadRow] = av.x;
        As[loadCol + 1][loadRow] = av.y;
        As[loadCol + 2][loadRow] = av.z;
        As[loadCol + 3][loadRow] = av.w;
        Bs[loadCol + 0][loadRow] = wv.x;
        Bs[loadCol + 1][loadRow] = wv.y;
        Bs[loadCol + 2][loadRow] = wv.z;
        Bs[loadCol + 3][loadRow] = wv.w;
        __syncthreads();

#pragma unroll
        for (int kk = 0; kk < 8; kk++) {
            float4 a01 = *(const float4*)&As[kk][ty * 8];
            float4 a23 = *(const float4*)&As[kk][ty * 8 + 4];
            float4 b01 = *(const float4*)&Bs[kk][tx * 8];
            float4 b23 = *(const float4*)&Bs[kk][tx * 8 + 4];
            float a[8] = {a01.x, a01.y, a01.z, a01.w, a23.x, a23.y, a23.z, a23.w};
            float b[8] = {b01.x, b01.y, b01.z, b01.w, b23.x, b23.y, b23.z, b23.w};
#pragma unroll
            for (int i = 0; i < 8; i++)
#pragma unroll
                for (int j = 0; j < 8; j++)
                    acc[i][j] = fmaf(a[i], b[j], acc[i][j]);
        }
        __syncthreads();
    }

    const int row = rowBase + ty * 8;
    const int col = colBase + tx * 8;
    float bv[8];
#pragma unroll
    for (int j = 0; j < 8; j++) bv[j] = bias[col + j];

#pragma unroll
    for (int i = 0; i < 8; i++) {
        float4 v0, v1;
        v0.x = acc[i][0] + bv[0]; v0.y = acc[i][1] + bv[1];
        v0.z = acc[i][2] + bv[2]; v0.w = acc[i][3] + bv[3];
        v1.x = acc[i][4] + bv[4]; v1.y = acc[i][5] + bv[5];
        v1.z = acc[i][6] + bv[6]; v1.w = acc[i][7] + bv[7];
        *(float4*)&C[(size_t)(row + i) * N + col + 0] = v0;
        *(float4*)&C[(size_t)(row + i) * N + col + 4] = v1;
    }
}

// ---------------------------------------------------------------------------
// Flash attention: grid (S/64, B*H). Block = 256 threads.
// Per block: 64 query rows x full 2048 keys in chunks of 64.
// Smem: Qt[d][r], Kt[d][c] (transposed, row pad 68 -> float4 OK),
//       Vs[c][d], Pt[c][r].
// Thread grid 16x16; thread (ty,tx) owns score/O micro-tile rows ty*4..+3.
// Online softmax reduced over the 16-lane row group via shfl.
// ---------------------------------------------------------------------------
#define SROW 68
#define FLASH_SMEM (4 * 64 * SROW * 4)

__global__ __launch_bounds__(256) void flash_attn_kernel(
    const float* __restrict__ qkv, float* __restrict__ attnbuf)
{
    extern __shared__ float sm[];
    float* Qt = sm;
    float* Kt = sm + 64 * SROW;
    float* Vs = sm + 2 * 64 * SROW;
    float* Pt = sm + 3 * 64 * SROW;

    const int tid = threadIdx.x;
    const int tx = tid & 15;
    const int ty = tid >> 4;
    const int q0 = blockIdx.x * 64;
    const int bh = blockIdx.y;
    const int b = bh >> 4;   // H = 16
    const int h = bh & 15;

    const float* qbase = qkv + (size_t)b * QKV_COLS + h * HDIM;
    const float* kbase = qbase + EMBED;
    const float* vbase = qbase + 2 * EMBED;

    // Load Q tile transposed, pre-scaled by 1/sqrt(64)
#pragma unroll
    for (int t = 0; t < 4; t++) {
        int lin = tid + t * 256;
        int r = lin >> 4;
        int d4 = (lin & 15) * 4;
        float4 v = *(const float4*)(qbase + (size_t)(q0 + r) * ROW_STRIDE + d4);
        Qt[(d4 + 0) * SROW + r] = v.x * 0.125f;
        Qt[(d4 + 1) * SROW + r] = v.y * 0.125f;
        Qt[(d4 + 2) * SROW + r] = v.z * 0.125f;
        Qt[(d4 + 3) * SROW + r] = v.w * 0.125f;
    }

    float m_i[4], l_i[4], o[4][4];
#pragma unroll
    for (int i = 0; i < 4; i++) {
        m_i[i] = -1e30f;
        l_i[i] = 0.f;
#pragma unroll
        for (int j = 0; j < 4; j++) o[i][j] = 0.f;
    }
    __syncthreads();

    for (int j0 = 0; j0 < S_LEN; j0 += 64) {
        // Load K chunk (transposed) and V chunk (natural)
#pragma unroll
        for (int t = 0; t < 4; t++) {
            int lin = tid + t * 256;
            int c = lin >> 4;
            int d4 = (lin & 15) * 4;
            float4 kv = *(const float4*)(kbase + (size_t)(j0 + c) * ROW_STRIDE + d4);
            Kt[(d4 + 0) * SROW + c] = kv.x;
            Kt[(d4 + 1) * SROW + c] = kv.y;
            Kt[(d4 + 2) * SROW + c] = kv.z;
            Kt[(d4 + 3) * SROW + c] = kv.w;
            float4 vv = *(const float4*)(vbase + (size_t)(j0 + c) * ROW_STRIDE + d4);
            *(float4*)&Vs[c * SROW + d4] = vv;
        }
        __syncthreads();

        // GEMM1: s[r][c] = sum_d Q[r][d] * K[c][d]
        float s[4][4];
#pragma unroll
        for (int i = 0; i < 4; i++)
#pragma unroll
            for (int j = 0; j < 4; j++) s[i][j] = 0.f;

#pragma unroll 4
        for (int d = 0; d < 64; d++) {
            float4 a  = *(const float4*)&Qt[d * SROW + ty * 4];
            float4 bq = *(const float4*)&Kt[d * SROW + tx * 4];
            s[0][0] = fmaf(a.x, bq.x, s[0][0]); s[0][1] = fmaf(a.x, bq.y, s[0][1]);
            s[0][2] = fmaf(a.x, bq.z, s[0][2]); s[0][3] = fmaf(a.x, bq.w, s[0][3]);
            s[1][0] = fmaf(a.y, bq.x, s[1][0]); s[1][1] = fmaf(a.y, bq.y, s[1][1]);
            s[1][2] = fmaf(a.y, bq.z, s[1][2]); s[1][3] = fmaf(a.y, bq.w, s[1][3]);
            s[2][0] = fmaf(a.z, bq.x, s[2][0]); s[2][1] = fmaf(a.z, bq.y, s[2][1]);
            s[2][2] = fmaf(a.z, bq.z, s[2][2]); s[2][3] = fmaf(a.z, bq.w, s[2][3]);
            s[3][0] = fmaf(a.w, bq.x, s[3][0]); s[3][1] = fmaf(a.w, bq.y, s[3][1]);
            s[3][2] = fmaf(a.w, bq.z, s[3][2]); s[3][3] = fmaf(a.w, bq.w, s[3][3]);
        }

        // Online softmax (per row; 16-lane row group shares ty)
#pragma unroll
        for (int i = 0; i < 4; i++) {
            float mx = fmaxf(fmaxf(s[i][0], s[i][1]), fmaxf(s[i][2], s[i][3]));
            mx = fmaxf(mx, __shfl_xor_sync(0xffffffffu, mx, 8));
            mx = fmaxf(mx, __shfl_xor_sync(0xffffffffu, mx, 4));
            mx = fmaxf(mx, __shfl_xor_sync(0xffffffffu, mx, 2));
            mx = fmaxf(mx, __shfl_xor_sync(0xffffffffu, mx, 1));
            float mn = fmaxf(m_i[i], mx);
            float alpha = __expf(m_i[i] - mn);
            m_i[i] = mn;
            float sum = 0.f;
#pragma unroll
            for (int j = 0; j < 4; j++) {
                s[i][j] = __expf(s[i][j] - mn);
                sum += s[i][j];
            }
            sum += __shfl_xor_sync(0xffffffffu, sum, 8);
            sum += __shfl_xor_sync(0xffffffffu, sum, 4);
            sum += __shfl_xor_sync(0xffffffffu, sum, 2);
            sum += __shfl_xor_sync(0xffffffffu, sum, 1);
            l_i[i] = l_i[i] * alpha + sum;
            o[i][0] *= alpha; o[i][1] *= alpha; o[i][2] *= alpha; o[i][3] *= alpha;
        }

        // Stage P transposed: Pt[c][r]
#pragma unroll
        for (int i = 0; i < 4; i++)
#pragma unroll
            for (int j = 0; j < 4; j++)
                Pt[(tx * 4 + j) * SROW + ty * 4 + i] = s[i][j];
        __syncthreads();

        // GEMM2: O[r][d] += sum_c P[r][c] * V[c][d]
#pragma unroll 4
        for (int c = 0; c < 64; c++) {
            float4 a  = *(const float4*)&Pt[c * SROW + ty * 4];
            float4 vv = *(const float4*)&Vs[c * SROW + tx * 4];
            o[0][0] = fmaf(a.x, vv.x, o[0][0]); o[0][1] = fmaf(a.x, vv.y, o[0][1]);
            o[0][2] = fmaf(a.x, vv.z, o[0][2]); o[0][3] = fmaf(a.x, vv.w, o[0][3]);
            o[1][0] = fmaf(a.y, vv.x, o[1][0]); o[1][1] = fmaf(a.y, vv.y, o[1][1]);
            o[1][2] = fmaf(a.y, vv.z, o[1][2]); o[1][3] = fmaf(a.y, vv.w, o[1][3]);
            o[2][0] = fmaf(a.z, vv.x, o[2][0]); o[2][1] = fmaf(a.z, vv.y, o[2][1]);
            o[2][2] = fmaf(a.z, vv.z, o[2][2]); o[2][3] = fmaf(a.z, vv.w, o[2][3]);
            o[3][0] = fmaf(a.w, vv.x, o[3][0]); o[3][1] = fmaf(a.w, vv.y, o[3][1]);
            o[3][2] = fmaf(a.w, vv.z, o[3][2]); o[3][3] = fmaf(a.w, vv.w, o[3][3]);
        }
        __syncthreads();
    }

    // Epilogue: normalize and store to attn buffer [S, B, E]
#pragma unroll
    for (int i = 0; i < 4; i++) {
        float inv = 1.f / l_i[i];
        int sg = q0 + ty * 4 + i;
        float4 outv;
        outv.x = o[i][0] * inv;
        outv.y = o[i][1] * inv;
        outv.z = o[i][2] * inv;
        outv.w = o[i][3] * inv;
        *(float4*)&attnbuf[(size_t)(sg * BATCH + b) * EMBED + h * HDIM + tx * 4] = outv;
    }
}

// ---------------------------------------------------------------------------
extern "C" void kernel_launch(void* const* d_in, const int* in_sizes, int n_in,
                              void* d_out, int out_size)
{
    (void)in_sizes; (void)n_in; (void)out_size;
    const float* x    = (const float*)d_in[0];
    const float* Win  = (const float*)d_in[1];
    const float* bin  = (const float*)d_in[2];
    const float* Wout = (const float*)d_in[3];
    const float* bout = (const float*)d_in[4];
    float* out = (float*)d_out;

    float* qkv = nullptr;
    float* attn = nullptr;
    cudaGetSymbolAddress((void**)&qkv, g_qkv);
    cudaGetSymbolAddress((void**)&attn, g_attn);

    // 1) QKV projection: [4096,1024] x [3072,1024]^T -> [4096,3072]
    sgemm_bias_kernel<<<dim3(QKV_COLS / 128, M_ROWS / 128), 256>>>(
        x, Win, bin, qkv, M_ROWS, QKV_COLS, EMBED);

    // 2) Flash attention over 64-query tiles per head
    cudaFuncSetAttribute(flash_attn_kernel,
                         cudaFuncAttributeMaxDynamicSharedMemorySize, FLASH_SMEM);
    flash_attn_kernel<<<dim3(S_LEN / 64, BATCH * HEADS), 256, FLASH_SMEM>>>(qkv, attn);

    // 3) Output projection: [4096,1024] x [1024,1024]^T -> [4096,1024]
    sgemm_bias_kernel<<<dim3(EMBED / 128, M_ROWS / 128), 256>>>(
        attn, Wout, bout, out, M_ROWS, EMBED, EMBED);
}

// round 3
// speedup vs baseline: 1.4842x; 1.4842x over previous
#include <cuda_runtime.h>
#include <cuda_bf16.h>
#include <cstdint>

// Problem constants
#define S_LEN 2048
#define BATCH 2
#define EMBED 1024
#define HEADS 16
#define HDIM  64
#define M_ROWS (S_LEN * BATCH)        // 4096
#define QKV_COLS (3 * EMBED)          // 3072
#define ROW_STRIDE (BATCH * QKV_COLS) // 6144 floats per seq step in qkv

// ---------------------------------------------------------------------------
// Scratch (device globals; no allocation in kernel_launch)
// ---------------------------------------------------------------------------
__device__ float g_qkv[(size_t)M_ROWS * QKV_COLS];   // [S*B, 3E]
__device__ float g_attn[(size_t)M_ROWS * EMBED];     // [S*B, E]
__device__ __align__(16) __nv_bfloat16 g_xhi[(size_t)M_ROWS * EMBED];
__device__ __align__(16) __nv_bfloat16 g_xlo[(size_t)M_ROWS * EMBED];
__device__ __align__(16) __nv_bfloat16 g_w1hi[(size_t)QKV_COLS * EMBED];
__device__ __align__(16) __nv_bfloat16 g_w1lo[(size_t)QKV_COLS * EMBED];
__device__ __align__(16) __nv_bfloat16 g_w2hi[(size_t)EMBED * EMBED];
__device__ __align__(16) __nv_bfloat16 g_w2lo[(size_t)EMBED * EMBED];
__device__ __align__(16) __nv_bfloat16 g_ahi[(size_t)M_ROWS * EMBED];
__device__ __align__(16) __nv_bfloat16 g_alo[(size_t)M_ROWS * EMBED];

// ---------------------------------------------------------------------------
// PTX helpers (baseline compute_103-safe: mma.sync + ldmatrix + cp.async)
// ---------------------------------------------------------------------------
__device__ __forceinline__ uint32_t smem_u32(const void* p) {
    uint32_t addr;
    asm("{ .reg .u64 t; cvta.to.shared.u64 t, %1; cvt.u32.u64 %0, t; }"
        : "=r"(addr) : "l"(p));
    return addr;
}

__device__ __forceinline__ void cp16(uint32_t dst, const void* src) {
    asm volatile("cp.async.cg.shared.global [%0], [%1], 16;" :: "r"(dst), "l"(src));
}
#define CP_COMMIT() asm volatile("cp.async.commit_group;" ::: "memory")
#define CP_WAIT1()  asm volatile("cp.async.wait_group 1;" ::: "memory")

#define LDSM_X4(r0, r1, r2, r3, addr) \
    asm volatile("ldmatrix.sync.aligned.m8n8.x4.shared.b16 {%0,%1,%2,%3}, [%4];" \
        : "=r"(r0), "=r"(r1), "=r"(r2), "=r"(r3) : "r"(addr))

__device__ __forceinline__ void mma16816(float* c, const uint32_t* a,
                                         const uint32_t b0, const uint32_t b1) {
    asm volatile(
        "mma.sync.aligned.m16n8k16.row.col.f32.bf16.bf16.f32 "
        "{%0,%1,%2,%3}, {%4,%5,%6,%7}, {%8,%9}, {%0,%1,%2,%3};"
        : "+f"(c[0]), "+f"(c[1]), "+f"(c[2]), "+f"(c[3])
        : "r"(a[0]), "r"(a[1]), "r"(a[2]), "r"(a[3]), "r"(b0), "r"(b1));
}

// ---------------------------------------------------------------------------
// fp32 -> bf16 hi/lo split (vectorized by 4)
// ---------------------------------------------------------------------------
__global__ __launch_bounds__(256) void split_bf16_kernel(
    const float4* __restrict__ in, ushort4* __restrict__ hi,
    ushort4* __restrict__ lo)
{
    int i = blockIdx.x * blockDim.x + threadIdx.x;
    float4 v = in[i];
    __nv_bfloat16 h0 = __float2bfloat16(v.x);
    __nv_bfloat16 h1 = __float2bfloat16(v.y);
    __nv_bfloat16 h2 = __float2bfloat16(v.z);
    __nv_bfloat16 h3 = __float2bfloat16(v.w);
    __nv_bfloat16 l0 = __float2bfloat16(v.x - __bfloat162float(h0));
    __nv_bfloat16 l1 = __float2bfloat16(v.y - __bfloat162float(h1));
    __nv_bfloat16 l2 = __float2bfloat16(v.z - __bfloat162float(h2));
    __nv_bfloat16 l3 = __float2bfloat16(v.w - __bfloat162float(h3));
    hi[i] = make_ushort4(__bfloat16_as_ushort(h0), __bfloat16_as_ushort(h1),
                         __bfloat16_as_ushort(h2), __bfloat16_as_ushort(h3));
    lo[i] = make_ushort4(__bfloat16_as_ushort(l0), __bfloat16_as_ushort(l1),
                         __bfloat16_as_ushort(l2), __bfloat16_as_ushort(l3));
}

// ---------------------------------------------------------------------------
// mma.sync GEMM:  C[M,Ntot] = Ahi*Whi^T + Ahi*Wlo^T + Alo*Whi^T + bias
// A: [M,1024] bf16 K-major.  W: [Ntot,1024] bf16 K-major.
// CTA tile 128x128, 8 warps (2 M x 4 N), warp tile 64x32.
// K staged 64 elems (128B rows, SW128 swizzle), double-buffered cp.async.
// grid = (Ntot/128, M/128), 256 threads.
// ---------------------------------------------------------------------------
#define GK 1024
#define KSTEP 64
#define NSTAGE (GK / KSTEP)          // 16
#define STAGE_BYTES 65536            // 4 mats x 128 rows x 128B
#define GEMM_SMEM (2 * STAGE_BYTES)  // 131072

__global__ __launch_bounds__(256) void gemm_mma_kernel(
    const __nv_bfloat16* __restrict__ Ahi, const __nv_bfloat16* __restrict__ Alo,
    const __nv_bfloat16* __restrict__ Whi, const __nv_bfloat16* __restrict__ Wlo,
    const float* __restrict__ bias, float* __restrict__ C, int Ntot)
{
    extern __shared__ char sm_raw[];
    const uint32_t smem_base = smem_u32(sm_raw);
    const int tid = threadIdx.x;
    const int wid = tid >> 5;
    const int lane = tid & 31;
    const int warpM = wid & 1;          // 2 warps over M
    const int warpN = wid >> 1;         // 4 warps over N
    const int rowBase = blockIdx.y * 128;
    const int colBase = blockIdx.x * 128;

    // ---- stage loader: 4096 x 16B cp.async per stage (16 per thread) ----
    auto load_stage = [&](int s, int buf) {
        const int k0 = s * KSTEP;
        const uint32_t base = smem_base + (uint32_t)buf * STAGE_BYTES;
#pragma unroll
        for (int i = 0; i < 16; i++) {
            int idx = tid + (i << 8);          // 0..4095
            int mat = idx >> 10;               // 0:Ahi 1:Alo 2:Whi 3:Wlo
            int r   = (idx >> 3) & 127;
            int c16 = idx & 7;
            const __nv_bfloat16* srcb =
                (mat == 0) ? Ahi : (mat == 1) ? Alo : (mat == 2) ? Whi : Wlo;
            int rowg = ((mat < 2) ? rowBase : colBase) + r;
            const void* src = srcb + (size_t)rowg * GK + k0 + c16 * 8;
            uint32_t dst = base + (uint32_t)(mat * 16384 + r * 128 +
                                             ((c16 ^ (r & 7)) * 16));
            cp16(dst, src);
        }
    };

    float acc[4][4][4];
#pragma unroll
    for (int mi = 0; mi < 4; mi++)
#pragma unroll
        for (int ni = 0; ni < 4; ni++)
#pragma unroll
            for (int j = 0; j < 4; j++) acc[mi][ni][j] = 0.f;

    // per-lane ldmatrix address components
    const int aRow = warpM * 64 + (lane & 15);      // + mi*16
    const int aHalf = lane >> 4;                    // col half (16B)
    const int bRow = warpN * 32 + ((lane >> 4) * 8) + (lane & 7);  // + np*16
    const int bHalf = (lane >> 3) & 1;

    load_stage(0, 0);
    CP_COMMIT();

    for (int s = 0; s < NSTAGE; s++) {
        const int buf = s & 1;
        if (s + 1 < NSTAGE) load_stage(s + 1, buf ^ 1);
        CP_COMMIT();
        CP_WAIT1();
        __syncthreads();

        const uint32_t base = smem_base + (uint32_t)buf * STAGE_BYTES;
#pragma unroll
        for (int kk = 0; kk < 4; kk++) {
            uint32_t ah[4][4], al[4][4], bh[2][4], bl[2][4];
#pragma unroll
            for (int mi = 0; mi < 4; mi++) {
                int r = aRow + mi * 16;
                int c16 = kk * 2 + aHalf;
                uint32_t off = (uint32_t)(r * 128 + ((c16 ^ (r & 7)) * 16));
                LDSM_X4(ah[mi][0], ah[mi][1], ah[mi][2], ah[mi][3], base + off);
                LDSM_X4(al[mi][0], al[mi][1], al[mi][2], al[mi][3],
                        base + 16384u + off);
            }
#pragma unroll
            for (int np = 0; np < 2; np++) {
                int r = bRow + np * 16;
                int c16 = kk * 2 + bHalf;
                uint32_t off = (uint32_t)(r * 128 + ((c16 ^ (r & 7)) * 16));
                LDSM_X4(bh[np][0], bh[np][1], bh[np][2], bh[np][3],
                        base + 32768u + off);
                LDSM_X4(bl[np][0], bl[np][1], bl[np][2], bl[np][3],
                        base + 49152u + off);
            }
#pragma unroll
            for (int mi = 0; mi < 4; mi++)
#pragma unroll
                for (int ni = 0; ni < 4; ni++) {
                    const int np = ni >> 1, sub = (ni & 1) * 2;
                    mma16816(acc[mi][ni], ah[mi], bh[np][sub], bh[np][sub + 1]);
                    mma16816(acc[mi][ni], ah[mi], bl[np][sub], bl[np][sub + 1]);
                    mma16816(acc[mi][ni], al[mi], bh[np][sub], bh[np][sub + 1]);
                }
        }
        __syncthreads();
    }

    // Epilogue: c0,c1 -> (row lane/4, cols 2*(lane%3)..); c2,c3 -> row+8
    const int erow = rowBase + warpM * 64 + (lane >> 2);
    const int ecol0 = colBase + warpN * 32 + (lane & 3) * 2;
#pragma unroll
    for (int ni = 0; ni < 4; ni++) {
        const int col = ecol0 + ni * 8;
        const float bx = bias[col], by = bias[col + 1];
#pragma unroll
        for (int mi = 0; mi < 4; mi++) {
            const int r0 = erow + mi * 16;
            float2 v0 = {acc[mi][ni][0] + bx, acc[mi][ni][1] + by};
            float2 v1 = {acc[mi][ni][2] + bx, acc[mi][ni][3] + by};
            *(float2*)&C[(size_t)r0 * Ntot + col] = v0;
            *(float2*)&C[(size_t)(r0 + 8) * Ntot + col] = v1;
        }
    }
}

// ---------------------------------------------------------------------------
// Flash attention (unchanged, known-good): grid (S/64, B*H), 256 threads.
// ---------------------------------------------------------------------------
#define SROW 68
#define FLASH_SMEM (4 * 64 * SROW * 4)

__global__ __launch_bounds__(256) void flash_attn_kernel(
    const float* __restrict__ qkv, float* __restrict__ attnbuf)
{
    extern __shared__ float sm[];
    float* Qt = sm;
    float* Kt = sm + 64 * SROW;
    float* Vs = sm + 2 * 64 * SROW;
    float* Pt = sm + 3 * 64 * SROW;

    const int tid = threadIdx.x;
    const int tx = tid & 15;
    const int ty = tid >> 4;
    const int q0 = blockIdx.x * 64;
    const int bh = blockIdx.y;
    const int b = bh >> 4;   // H = 16
    const int h = bh & 15;

    const float* qbase = qkv + (size_t)b * QKV_COLS + h * HDIM;
    const float* kbase = qbase + EMBED;
    const float* vbase = qbase + 2 * EMBED;

#pragma unroll
    for (int t = 0; t < 4; t++) {
        int lin = tid + t * 256;
        int r = lin >> 4;
        int d4 = (lin & 15) * 4;
        float4 v = *(const float4*)(qbase + (size_t)(q0 + r) * ROW_STRIDE + d4);
        Qt[(d4 + 0) * SROW + r] = v.x * 0.125f;
        Qt[(d4 + 1) * SROW + r] = v.y * 0.125f;
        Qt[(d4 + 2) * SROW + r] = v.z * 0.125f;
        Qt[(d4 + 3) * SROW + r] = v.w * 0.125f;
    }

    float m_i[4], l_i[4], o[4][4];
#pragma unroll
    for (int i = 0; i < 4; i++) {
        m_i[i] = -1e30f;
        l_i[i] = 0.f;
#pragma unroll
        for (int j = 0; j < 4; j++) o[i][j] = 0.f;
    }
    __syncthreads();

    for (int j0 = 0; j0 < S_LEN; j0 += 64) {
#pragma unroll
        for (int t = 0; t < 4; t++) {
            int lin = tid + t * 256;
            int c = lin >> 4;
            int d4 = (lin & 15) * 4;
            float4 kv = *(const float4*)(kbase + (size_t)(j0 + c) * ROW_STRIDE + d4);
            Kt[(d4 + 0) * SROW + c] = kv.x;
            Kt[(d4 + 1) * SROW + c] = kv.y;
            Kt[(d4 + 2) * SROW + c] = kv.z;
            Kt[(d4 + 3) * SROW + c] = kv.w;
            float4 vv = *(const float4*)(vbase + (size_t)(j0 + c) * ROW_STRIDE + d4);
            *(float4*)&Vs[c * SROW + d4] = vv;
        }
        __syncthreads();

        float s[4][4];
#pragma unroll
        for (int i = 0; i < 4; i++)
#pragma unroll
            for (int j = 0; j < 4; j++) s[i][j] = 0.f;

#pragma unroll 4
        for (int d = 0; d < 64; d++) {
            float4 a  = *(const float4*)&Qt[d * SROW + ty * 4];
            float4 bq = *(const float4*)&Kt[d * SROW + tx * 4];
            s[0][0] = fmaf(a.x, bq.x, s[0][0]); s[0][1] = fmaf(a.x, bq.y, s[0][1]);
            s[0][2] = fmaf(a.x, bq.z, s[0][2]); s[0][3] = fmaf(a.x, bq.w, s[0][3]);
            s[1][0] = fmaf(a.y, bq.x, s[1][0]); s[1][1] = fmaf(a.y, bq.y, s[1][1]);
            s[1][2] = fmaf(a.y, bq.z, s[1][2]); s[1][3] = fmaf(a.y, bq.w, s[1][3]);
            s[2][0] = fmaf(a.z, bq.x, s[2][0]); s[2][1] = fmaf(a.z, bq.y, s[2][1]);
            s[2][2] = fmaf(a.z, bq.z, s[2][2]); s[2][3] = fmaf(a.z, bq.w, s[2][3]);
            s[3][0] = fmaf(a.w, bq.x, s[3][0]); s[3][1] = fmaf(a.w, bq.y, s[3][1]);
            s[3][2] = fmaf(a.w, bq.z, s[3][2]); s[3][3] = fmaf(a.w, bq.w, s[3][3]);
        }

#pragma unroll
        for (int i = 0; i < 4; i++) {
            float mx = fmaxf(fmaxf(s[i][0], s[i][1]), fmaxf(s[i][2], s[i][3]));
            mx = fmaxf(mx, __shfl_xor_sync(0xffffffffu, mx, 8));
            mx = fmaxf(mx, __shfl_xor_sync(0xffffffffu, mx, 4));
            mx = fmaxf(mx, __shfl_xor_sync(0xffffffffu, mx, 2));
            mx = fmaxf(mx, __shfl_xor_sync(0xffffffffu, mx, 1));
            float mn = fmaxf(m_i[i], mx);
            float alpha = __expf(m_i[i] - mn);
            m_i[i] = mn;
            float sum = 0.f;
#pragma unroll
            for (int j = 0; j < 4; j++) {
                s[i][j] = __expf(s[i][j] - mn);
                sum += s[i][j];
            }
            sum += __shfl_xor_sync(0xffffffffu, sum, 8);
            sum += __shfl_xor_sync(0xffffffffu, sum, 4);
            sum += __shfl_xor_sync(0xffffffffu, sum, 2);
            sum += __shfl_xor_sync(0xffffffffu, sum, 1);
            l_i[i] = l_i[i] * alpha + sum;
            o[i][0] *= alpha; o[i][1] *= alpha; o[i][2] *= alpha; o[i][3] *= alpha;
        }

#pragma unroll
        for (int i = 0; i < 4; i++)
#pragma unroll
            for (int j = 0; j < 4; j++)
                Pt[(tx * 4 + j) * SROW + ty * 4 + i] = s[i][j];
        __syncthreads();

#pragma unroll 4
        for (int c = 0; c < 64; c++) {
            float4 a  = *(const float4*)&Pt[c * SROW + ty * 4];
            float4 vv = *(const float4*)&Vs[c * SROW + tx * 4];
            o[0][0] = fmaf(a.x, vv.x, o[0][0]); o[0][1] = fmaf(a.x, vv.y, o[0][1]);
            o[0][2] = fmaf(a.x, vv.z, o[0][2]); o[0][3] = fmaf(a.x, vv.w, o[0][3]);
            o[1][0] = fmaf(a.y, vv.x, o[1][0]); o[1][1] = fmaf(a.y, vv.y, o[1][1]);
            o[1][2] = fmaf(a.y, vv.z, o[1][2]); o[1][3] = fmaf(a.y, vv.w, o[1][3]);
            o[2][0] = fmaf(a.z, vv.x, o[2][0]); o[2][1] = fmaf(a.z, vv.y, o[2][1]);
            o[2][2] = fmaf(a.z, vv.z, o[2][2]); o[2][3] = fmaf(a.z, vv.w, o[2][3]);
            o[3][0] = fmaf(a.w, vv.x, o[3][0]); o[3][1] = fmaf(a.w, vv.y, o[3][1]);
            o[3][2] = fmaf(a.w, vv.z, o[3][2]); o[3][3] = fmaf(a.w, vv.w, o[3][3]);
        }
        __syncthreads();
    }

#pragma unroll
    for (int i = 0; i < 4; i++) {
        float inv = 1.f / l_i[i];
        int sg = q0 + ty * 4 + i;
        float4 outv;
        outv.x = o[i][0] * inv;
        outv.y = o[i][1] * inv;
        outv.z = o[i][2] * inv;
        outv.w = o[i][3] * inv;
        *(float4*)&attnbuf[(size_t)(sg * BATCH + b) * EMBED + h * HDIM + tx * 4] = outv;
    }
}

// ---------------------------------------------------------------------------
extern "C" void kernel_launch(void* const* d_in, const int* in_sizes, int n_in,
                              void* d_out, int out_size)
{
    (void)in_sizes; (void)n_in; (void)out_size;
    const float* x    = (const float*)d_in[0];
    const float* Win  = (const float*)d_in[1];
    const float* bin  = (const float*)d_in[2];
    const float* Wout = (const float*)d_in[3];
    const float* bout = (const float*)d_in[4];
    float* out = (float*)d_out;

    float *qkv = nullptr, *attn = nullptr;
    __nv_bfloat16 *xhi, *xlo, *w1hi, *w1lo, *w2hi, *w2lo, *ahi, *alo;
    cudaGetSymbolAddress((void**)&qkv, g_qkv);
    cudaGetSymbolAddress((void**)&attn, g_attn);
    cudaGetSymbolAddress((void**)&xhi, g_xhi);
    cudaGetSymbolAddress((void**)&xlo, g_xlo);
    cudaGetSymbolAddress((void**)&w1hi, g_w1hi);
    cudaGetSymbolAddress((void**)&w1lo, g_w1lo);
    cudaGetSymbolAddress((void**)&w2hi, g_w2hi);
    cudaGetSymbolAddress((void**)&w2lo, g_w2lo);
    cudaGetSymbolAddress((void**)&ahi, g_ahi);
    cudaGetSymbolAddress((void**)&alo, g_alo);

    cudaFuncSetAttribute(gemm_mma_kernel,
                         cudaFuncAttributeMaxDynamicSharedMemorySize, GEMM_SMEM);
    cudaFuncSetAttribute(flash_attn_kernel,
                         cudaFuncAttributeMaxDynamicSharedMemorySize, FLASH_SMEM);

    // 0) fp32 -> bf16 hi/lo splits
    split_bf16_kernel<<<(M_ROWS * EMBED) / 1024, 256>>>(
        (const float4*)x, (ushort4*)xhi, (ushort4*)xlo);
    split_bf16_kernel<<<(QKV_COLS * EMBED) / 1024, 256>>>(
        (const float4*)Win, (ushort4*)w1hi, (ushort4*)w1lo);
    split_bf16_kernel<<<(EMBED * EMBED) / 1024, 256>>>(
        (const float4*)Wout, (ushort4*)w2hi, (ushort4*)w2lo);

    // 1) QKV projection on tensor cores (mma.sync): [4096,1024]x[3072,1024]^T
    gemm_mma_kernel<<<dim3(QKV_COLS / 128, M_ROWS / 128), 256, GEMM_SMEM>>>(
        xhi, xlo, w1hi, w1lo, bin, qkv, QKV_COLS);

    // 2) Flash attention
    flash_attn_kernel<<<dim3(S_LEN / 64, BATCH * HEADS), 256, FLASH_SMEM>>>(qkv, attn);

    // 3) split attn output, then out projection on tensor cores
    split_bf16_kernel<<<(M_ROWS * EMBED) / 1024, 256>>>(
        (const float4*)attn, (ushort4*)ahi, (ushort4*)alo);
    gemm_mma_kernel<<<dim3(EMBED / 128, M_ROWS / 128), 256, GEMM_SMEM>>>(
        ahi, alo, w2hi, w2lo, bout, out, EMBED);
}

// round 4
// speedup vs baseline: 3.1268x; 2.1067x over previous
#include <cuda_runtime.h>
#include <cuda_bf16.h>
#include <cstdint>

// Problem constants
#define S_LEN 2048
#define BATCH 2
#define EMBED 1024
#define HEADS 16
#define HDIM  64
#define M_ROWS (S_LEN * BATCH)        // 4096
#define QKV_COLS (3 * EMBED)          // 3072

// ---------------------------------------------------------------------------
// Scratch (device globals; no allocation in kernel_launch)
// ---------------------------------------------------------------------------
__device__ __align__(16) __nv_bfloat16 g_xhi[(size_t)M_ROWS * EMBED];
__device__ __align__(16) __nv_bfloat16 g_xlo[(size_t)M_ROWS * EMBED];
__device__ __align__(16) __nv_bfloat16 g_w1hi[(size_t)QKV_COLS * EMBED];
__device__ __align__(16) __nv_bfloat16 g_w1lo[(size_t)QKV_COLS * EMBED];
__device__ __align__(16) __nv_bfloat16 g_w2hi[(size_t)EMBED * EMBED];
__device__ __align__(16) __nv_bfloat16 g_w2lo[(size_t)EMBED * EMBED];
__device__ __align__(16) __nv_bfloat16 g_qkvhi[(size_t)M_ROWS * QKV_COLS];
__device__ __align__(16) __nv_bfloat16 g_qkvlo[(size_t)M_ROWS * QKV_COLS];
__device__ __align__(16) __nv_bfloat16 g_ahi[(size_t)M_ROWS * EMBED];
__device__ __align__(16) __nv_bfloat16 g_alo[(size_t)M_ROWS * EMBED];

// ---------------------------------------------------------------------------
// PTX helpers (baseline compute_103-safe: mma.sync + ldmatrix + cp.async)
// ---------------------------------------------------------------------------
__device__ __forceinline__ uint32_t smem_u32(const void* p) {
    uint32_t addr;
    asm("{ .reg .u64 t; cvta.to.shared.u64 t, %1; cvt.u32.u64 %0, t; }"
        : "=r"(addr) : "l"(p));
    return addr;
}

__device__ __forceinline__ void cp16(uint32_t dst, const void* src) {
    asm volatile("cp.async.cg.shared.global [%0], [%1], 16;" :: "r"(dst), "l"(src));
}
#define CP_COMMIT() asm volatile("cp.async.commit_group;" ::: "memory")
#define CP_WAIT1()  asm volatile("cp.async.wait_group 1;" ::: "memory")

#define LDSM_X4(r0, r1, r2, r3, addr) \
    asm volatile("ldmatrix.sync.aligned.m8n8.x4.shared.b16 {%0,%1,%2,%3}, [%4];" \
        : "=r"(r0), "=r"(r1), "=r"(r2), "=r"(r3) : "r"(addr))

#define LDSM_X4_T(r0, r1, r2, r3, addr) \
    asm volatile("ldmatrix.sync.aligned.m8n8.x4.trans.shared.b16 {%0,%1,%2,%3}, [%4];" \
        : "=r"(r0), "=r"(r1), "=r"(r2), "=r"(r3) : "r"(addr))

__device__ __forceinline__ void mma16816(float* c, const uint32_t* a,
                                         const uint32_t b0, const uint32_t b1) {
    asm volatile(
        "mma.sync.aligned.m16n8k16.row.col.f32.bf16.bf16.f32 "
        "{%0,%1,%2,%3}, {%4,%5,%6,%7}, {%8,%9}, {%0,%1,%2,%3};"
        : "+f"(c[0]), "+f"(c[1]), "+f"(c[2]), "+f"(c[3])
        : "r"(a[0]), "r"(a[1]), "r"(a[2]), "r"(a[3]), "r"(b0), "r"(b1));
}

// split two floats into packed bf16x2 hi and lo parts
__device__ __forceinline__ void pack_split(float f0, float f1,
                                           uint32_t& hi, uint32_t& lo) {
    __nv_bfloat162 h = __floats2bfloat162_rn(f0, f1);
    float2 hf = __bfloat1622float2(h);
    __nv_bfloat162 l = __floats2bfloat162_rn(f0 - hf.x, f1 - hf.y);
    hi = *reinterpret_cast<uint32_t*>(&h);
    lo = *reinterpret_cast<uint32_t*>(&l);
}

__device__ __forceinline__ void split2_store(float v0, float v1,
                                             __nv_bfloat16* hip,
                                             __nv_bfloat16* lop) {
    __nv_bfloat162 h = __floats2bfloat162_rn(v0, v1);
    float2 hf = __bfloat1622float2(h);
    __nv_bfloat162 l = __floats2bfloat162_rn(v0 - hf.x, v1 - hf.y);
    *reinterpret_cast<__nv_bfloat162*>(hip) = h;
    *reinterpret_cast<__nv_bfloat162*>(lop) = l;
}

// ---------------------------------------------------------------------------
// fp32 -> bf16 hi/lo split (vectorized by 4)
// ---------------------------------------------------------------------------
__global__ __launch_bounds__(256) void split_bf16_kernel(
    const float4* __restrict__ in, ushort4* __restrict__ hi,
    ushort4* __restrict__ lo)
{
    int i = blockIdx.x * blockDim.x + threadIdx.x;
    float4 v = in[i];
    __nv_bfloat16 h0 = __float2bfloat16(v.x);
    __nv_bfloat16 h1 = __float2bfloat16(v.y);
    __nv_bfloat16 h2 = __float2bfloat16(v.z);
    __nv_bfloat16 h3 = __float2bfloat16(v.w);
    __nv_bfloat16 l0 = __float2bfloat16(v.x - __bfloat162float(h0));
    __nv_bfloat16 l1 = __float2bfloat16(v.y - __bfloat162float(h1));
    __nv_bfloat16 l2 = __float2bfloat16(v.z - __bfloat162float(h2));
    __nv_bfloat16 l3 = __float2bfloat16(v.w - __bfloat162float(h3));
    hi[i] = make_ushort4(__bfloat16_as_ushort(h0), __bfloat16_as_ushort(h1),
                         __bfloat16_as_ushort(h2), __bfloat16_as_ushort(h3));
    lo[i] = make_ushort4(__bfloat16_as_ushort(l0), __bfloat16_as_ushort(l1),
                         __bfloat16_as_ushort(l2), __bfloat16_as_ushort(l3));
}

// ---------------------------------------------------------------------------
// mma.sync GEMM:  C[M,Ntot] = Ahi*Whi^T + Ahi*Wlo^T + Alo*Whi^T + bias
// Output either fp32 (Cf) or bf16 hi/lo split (Chi/Clo); columns < qcols are
// scaled by 0.125 (Q scaling for the QKV projection; exact in bf16).
// CTA tile 128x128, 8 warps (2 M x 4 N), warp tile 64x32.
// ---------------------------------------------------------------------------
#define GK 1024
#define KSTEP 64
#define NSTAGE (GK / KSTEP)          // 16
#define STAGE_BYTES 65536            // 4 mats x 128 rows x 128B
#define GEMM_SMEM (2 * STAGE_BYTES)  // 131072

__global__ __launch_bounds__(256) void gemm_mma_kernel(
    const __nv_bfloat16* __restrict__ Ahi, const __nv_bfloat16* __restrict__ Alo,
    const __nv_bfloat16* __restrict__ Whi, const __nv_bfloat16* __restrict__ Wlo,
    const float* __restrict__ bias, float* __restrict__ Cf,
    __nv_bfloat16* __restrict__ Chi, __nv_bfloat16* __restrict__ Clo,
    int Ntot, int qcols)
{
    extern __shared__ char sm_raw[];
    const uint32_t smem_base = smem_u32(sm_raw);
    const int tid = threadIdx.x;
    const int wid = tid >> 5;
    const int lane = tid & 31;
    const int warpM = wid & 1;
    const int warpN = wid >> 1;
    const int rowBase = blockIdx.y * 128;
    const int colBase = blockIdx.x * 128;

    auto load_stage = [&](int s, int buf) {
        const int k0 = s * KSTEP;
        const uint32_t base = smem_base + (uint32_t)buf * STAGE_BYTES;
#pragma unroll
        for (int i = 0; i < 16; i++) {
            int idx = tid + (i << 8);
            int mat = idx >> 10;
            int r   = (idx >> 3) & 127;
            int c16 = idx & 7;
            const __nv_bfloat16* srcb =
                (mat == 0) ? Ahi : (mat == 1) ? Alo : (mat == 2) ? Whi : Wlo;
            int rowg = ((mat < 2) ? rowBase : colBase) + r;
            const void* src = srcb + (size_t)rowg * GK + k0 + c16 * 8;
            uint32_t dst = base + (uint32_t)(mat * 16384 + r * 128 +
                                             ((c16 ^ (r & 7)) * 16));
            cp16(dst, src);
        }
    };

    float acc[4][4][4];
#pragma unroll
    for (int mi = 0; mi < 4; mi++)
#pragma unroll
        for (int ni = 0; ni < 4; ni++)
#pragma unroll
            for (int j = 0; j < 4; j++) acc[mi][ni][j] = 0.f;

    const int aRow = warpM * 64 + (lane & 15);
    const int aHalf = lane >> 4;
    const int bRow = warpN * 32 + ((lane >> 4) * 8) + (lane & 7);
    const int bHalf = (lane >> 3) & 1;

    load_stage(0, 0);
    CP_COMMIT();

    for (int s = 0; s < NSTAGE; s++) {
        const int buf = s & 1;
        if (s + 1 < NSTAGE) load_stage(s + 1, buf ^ 1);
        CP_COMMIT();
        CP_WAIT1();
        __syncthreads();

        const uint32_t base = smem_base + (uint32_t)buf * STAGE_BYTES;
#pragma unroll
        for (int kk = 0; kk < 4; kk++) {
            uint32_t ah[4][4], al[4][4], bh[2][4], bl[2][4];
#pragma unroll
            for (int mi = 0; mi < 4; mi++) {
                int r = aRow + mi * 16;
                int c16 = kk * 2 + aHalf;
                uint32_t off = (uint32_t)(r * 128 + ((c16 ^ (r & 7)) * 16));
                LDSM_X4(ah[mi][0], ah[mi][1], ah[mi][2], ah[mi][3], base + off);
                LDSM_X4(al[mi][0], al[mi][1], al[mi][2], al[mi][3],
                        base + 16384u + off);
            }
#pragma unroll
            for (int np = 0; np < 2; np++) {
                int r = bRow + np * 16;
                int c16 = kk * 2 + bHalf;
                uint32_t off = (uint32_t)(r * 128 + ((c16 ^ (r & 7)) * 16));
                LDSM_X4(bh[np][0], bh[np][1], bh[np][2], bh[np][3],
                        base + 32768u + off);
                LDSM_X4(bl[np][0], bl[np][1], bl[np][2], bl[np][3],
                        base + 49152u + off);
            }
#pragma unroll
            for (int mi = 0; mi < 4; mi++)
#pragma unroll
                for (int ni = 0; ni < 4; ni++) {
                    const int np = ni >> 1, sub = (ni & 1) * 2;
                    mma16816(acc[mi][ni], ah[mi], bh[np][sub], bh[np][sub + 1]);
                    mma16816(acc[mi][ni], ah[mi], bl[np][sub], bl[np][sub + 1]);
                    mma16816(acc[mi][ni], al[mi], bh[np][sub], bh[np][sub + 1]);
                }
        }
        __syncthreads();
    }

    const int erow = rowBase + warpM * 64 + (lane >> 2);
    const int ecol0 = colBase + warpN * 32 + (lane & 3) * 2;
#pragma unroll
    for (int ni = 0; ni < 4; ni++) {
        const int col = ecol0 + ni * 8;
        const float sc = (col < qcols) ? 0.125f : 1.f;
        const float bx = bias[col], by = bias[col + 1];
#pragma unroll
        for (int mi = 0; mi < 4; mi++) {
            const int r0 = erow + mi * 16;
            float v0 = (acc[mi][ni][0] + bx) * sc;
            float v1 = (acc[mi][ni][1] + by) * sc;
            float v2 = (acc[mi][ni][2] + bx) * sc;
            float v3 = (acc[mi][ni][3] + by) * sc;
            if (Cf) {
                *(float2*)&Cf[(size_t)r0 * Ntot + col] = make_float2(v0, v1);
                *(float2*)&Cf[(size_t)(r0 + 8) * Ntot + col] = make_float2(v2, v3);
            } else {
                split2_store(v0, v1, Chi + (size_t)r0 * Ntot + col,
                             Clo + (size_t)r0 * Ntot + col);
                split2_store(v2, v3, Chi + (size_t)(r0 + 8) * Ntot + col,
                             Clo + (size_t)(r0 + 8) * Ntot + col);
            }
        }
    }
}

// ---------------------------------------------------------------------------
// Flash attention on mma.sync bf16 (hi/lo split everywhere).
// grid (S/128, B*H), 256 threads (8 warps x 16 q rows each).
// smem: Qhi/Qlo [128x64] + double-buffered {Khi,Klo,Vhi,Vlo}[64x64].
// ---------------------------------------------------------------------------
#define FL_SMEM 98304
#define NCHUNK (S_LEN / 64)   // 32

__global__ __launch_bounds__(256) void flash_mma_kernel(
    const __nv_bfloat16* __restrict__ qh, const __nv_bfloat16* __restrict__ ql,
    __nv_bfloat16* __restrict__ ohi, __nv_bfloat16* __restrict__ olo)
{
    extern __shared__ char sm_raw[];
    const uint32_t sb = smem_u32(sm_raw);
    const int tid = threadIdx.x;
    const int wid = tid >> 5;
    const int lane = tid & 31;
    const int q0 = blockIdx.x * 128;
    const int b = blockIdx.y >> 4;
    const int h = blockIdx.y & 15;
    const int qcol = h * HDIM;
    const int kcol = EMBED + h * HDIM;
    const int vcol = 2 * EMBED + h * HDIM;

    // ---- load Q tile (hi+lo), 2048 cp16 ----
#pragma unroll
    for (int i = 0; i < 8; i++) {
        int idx = tid + (i << 8);
        int mat = idx >> 10;            // 0: hi, 1: lo
        int r = (idx >> 3) & 127;
        int c16 = idx & 7;
        const __nv_bfloat16* sp = mat ? ql : qh;
        const void* src = sp + (size_t)((q0 + r) * 2 + b) * QKV_COLS + qcol + c16 * 8;
        uint32_t dst = sb + (uint32_t)(mat * 16384 + r * 128 +
                                       ((c16 ^ (r & 7)) * 16));
        cp16(dst, src);
    }
    CP_COMMIT();

    auto load_kv = [&](int j0, int buf) {
        const uint32_t base = sb + 32768u + (uint32_t)buf * 32768u;
#pragma unroll
        for (int i = 0; i < 8; i++) {
            int idx = tid + (i << 8);
            int mat = idx >> 9;         // 0:KH 1:KL 2:VH 3:VL
            int r = (idx >> 3) & 63;
            int c16 = idx & 7;
            const __nv_bfloat16* sp = (mat & 1) ? ql : qh;
            int colb = (mat >> 1) ? vcol : kcol;
            const void* src = sp + (size_t)((j0 + r) * 2 + b) * QKV_COLS + colb + c16 * 8;
            uint32_t dst = base + (uint32_t)(mat * 8192 + r * 128 +
                                             ((c16 ^ (r & 7)) * 16));
            cp16(dst, src);
        }
    };

    load_kv(0, 0);
    CP_COMMIT();

    // wait for Q (leave chunk0 in flight)
    CP_WAIT1();
    __syncthreads();

    // ---- Q fragments into registers ----
    uint32_t aqh[4][4], aql[4][4];
    {
        int r = wid * 16 + (lane & 15);
#pragma unroll
        for (int kk = 0; kk < 4; kk++) {
            int c16 = kk * 2 + (lane >> 4);
            uint32_t off = (uint32_t)(r * 128 + ((c16 ^ (r & 7)) * 16));
            LDSM_X4(aqh[kk][0], aqh[kk][1], aqh[kk][2], aqh[kk][3], sb + off);
            LDSM_X4(aql[kk][0], aql[kk][1], aql[kk][2], aql[kk][3],
                    sb + 16384u + off);
        }
    }

    float O[8][4];
#pragma unroll
    for (int ni = 0; ni < 8; ni++)
#pragma unroll
        for (int j = 0; j < 4; j++) O[ni][j] = 0.f;
    float m0 = -1e30f, m1 = -1e30f, l0 = 0.f, l1 = 0.f;

    for (int s = 0; s < NCHUNK; s++) {
        if (s + 1 < NCHUNK) load_kv((s + 1) * 64, (s + 1) & 1);
        CP_COMMIT();
        CP_WAIT1();
        __syncthreads();

        const uint32_t kb = sb + 32768u + (uint32_t)(s & 1) * 32768u;

        // ---- QK^T ----
        float sc[8][4];
#pragma unroll
        for (int ni = 0; ni < 8; ni++)
#pragma unroll
            for (int j = 0; j < 4; j++) sc[ni][j] = 0.f;

#pragma unroll
        for (int kk = 0; kk < 4; kk++) {
            uint32_t kh[4][4], kl[4][4];
            int rb = ((lane >> 4) * 8) + (lane & 7);
            int c16 = kk * 2 + ((lane >> 3) & 1);
#pragma unroll
            for (int np = 0; np < 4; np++) {
                int r = rb + np * 16;
                uint32_t off = (uint32_t)(r * 128 + ((c16 ^ (r & 7)) * 16));
                LDSM_X4(kh[np][0], kh[np][1], kh[np][2], kh[np][3], kb + off);
                LDSM_X4(kl[np][0], kl[np][1], kl[np][2], kl[np][3],
                        kb + 8192u + off);
            }
#pragma unroll
            for (int ni = 0; ni < 8; ni++) {
                const int np = ni >> 1, sub = (ni & 1) * 2;
                mma16816(sc[ni], aqh[kk], kh[np][sub], kh[np][sub + 1]);
                mma16816(sc[ni], aqh[kk], kl[np][sub], kl[np][sub + 1]);
                mma16816(sc[ni], aql[kk], kh[np][sub], kh[np][sub + 1]);
            }
        }

        // ---- online softmax (two row-halves per thread) ----
#pragma unroll
        for (int hh = 0; hh < 2; hh++) {
            const int j0 = hh * 2, j1 = hh * 2 + 1;
            float& m = hh ? m1 : m0;
            float& l = hh ? l1 : l0;
            float mx = -1e30f;
#pragma unroll
            for (int ni = 0; ni < 8; ni++)
                mx = fmaxf(mx, fmaxf(sc[ni][j0], sc[ni][j1]));
            mx = fmaxf(mx, __shfl_xor_sync(0xffffffffu, mx, 1));
            mx = fmaxf(mx, __shfl_xor_sync(0xffffffffu, mx, 2));
            float mn = fmaxf(m, mx);
            float alpha = __expf(m - mn);
            m = mn;
            float sum = 0.f;
#pragma unroll
            for (int ni = 0; ni < 8; ni++) {
                sc[ni][j0] = __expf(sc[ni][j0] - mn);
                sc[ni][j1] = __expf(sc[ni][j1] - mn);
                sum += sc[ni][j0] + sc[ni][j1];
            }
            sum += __shfl_xor_sync(0xffffffffu, sum, 1);
            sum += __shfl_xor_sync(0xffffffffu, sum, 2);
            l = l * alpha + sum;
#pragma unroll
            for (int ni = 0; ni < 8; ni++) {
                O[ni][j0] *= alpha;
                O[ni][j1] *= alpha;
            }
        }

        // ---- P @ V ----
#pragma unroll
        for (int kk2 = 0; kk2 < 4; kk2++) {
            uint32_t ph[4], pl[4];
            pack_split(sc[2 * kk2][0],     sc[2 * kk2][1],     ph[0], pl[0]);
            pack_split(sc[2 * kk2][2],     sc[2 * kk2][3],     ph[1], pl[1]);
            pack_split(sc[2 * kk2 + 1][0], sc[2 * kk2 + 1][1], ph[2], pl[2]);
            pack_split(sc[2 * kk2 + 1][2], sc[2 * kk2 + 1][3], ph[3], pl[3]);

            uint32_t vh[4][4], vl[4][4];
            int g = lane >> 3;
            int row = kk2 * 16 + (g & 1) * 8 + (lane & 7);
#pragma unroll
            for (int g4 = 0; g4 < 4; g4++) {
                int c16 = g4 * 2 + (g >> 1);
                uint32_t off = (uint32_t)(row * 128 + ((c16 ^ (row & 7)) * 16));
                LDSM_X4_T(vh[g4][0], vh[g4][1], vh[g4][2], vh[g4][3],
                          kb + 16384u + off);
                LDSM_X4_T(vl[g4][0], vl[g4][1], vl[g4][2], vl[g4][3],
                          kb + 24576u + off);
            }
#pragma unroll
            for (int ni = 0; ni < 8; ni++) {
                const int g4 = ni >> 1, sub = (ni & 1) * 2;
                mma16816(O[ni], ph, vh[g4][sub], vh[g4][sub + 1]);
                mma16816(O[ni], ph, vl[g4][sub], vl[g4][sub + 1]);
                mma16816(O[ni], pl, vh[g4][sub], vh[g4][sub + 1]);
            }
        }
        __syncthreads();
    }

    // ---- epilogue: normalize, split hi/lo, store ----
    const float inv0 = 1.f / l0;
    const float inv1 = 1.f / l1;
    const int sA = q0 + wid * 16 + (lane >> 2);
    const size_t rowA = (size_t)(sA * 2 + b) * EMBED;
    const size_t rowB = (size_t)((sA + 8) * 2 + b) * EMBED;
    const int colb = h * HDIM + (lane & 3) * 2;
#pragma unroll
    for (int ni = 0; ni < 8; ni++) {
        const int col = colb + ni * 8;
        split2_store(O[ni][0] * inv0, O[ni][1] * inv0,
                     ohi + rowA + col, olo + rowA + col);
        split2_store(O[ni][2] * inv1, O[ni][3] * inv1,
                     ohi + rowB + col, olo + rowB + col);
    }
}

// ---------------------------------------------------------------------------
extern "C" void kernel_launch(void* const* d_in, const int* in_sizes, int n_in,
                              void* d_out, int out_size)
{
    (void)in_sizes; (void)n_in; (void)out_size;
    const float* x    = (const float*)d_in[0];
    const float* Win  = (const float*)d_in[1];
    const float* bin  = (const float*)d_in[2];
    const float* Wout = (const float*)d_in[3];
    const float* bout = (const float*)d_in[4];
    float* out = (float*)d_out;

    __nv_bfloat16 *xhi, *xlo, *w1hi, *w1lo, *w2hi, *w2lo;
    __nv_bfloat16 *qkvhi, *qkvlo, *ahi, *alo;
    cudaGetSymbolAddress((void**)&xhi, g_xhi);
    cudaGetSymbolAddress((void**)&xlo, g_xlo);
    cudaGetSymbolAddress((void**)&w1hi, g_w1hi);
    cudaGetSymbolAddress((void**)&w1lo, g_w1lo);
    cudaGetSymbolAddress((void**)&w2hi, g_w2hi);
    cudaGetSymbolAddress((void**)&w2lo, g_w2lo);
    cudaGetSymbolAddress((void**)&qkvhi, g_qkvhi);
    cudaGetSymbolAddress((void**)&qkvlo, g_qkvlo);
    cudaGetSymbolAddress((void**)&ahi, g_ahi);
    cudaGetSymbolAddress((void**)&alo, g_alo);

    cudaFuncSetAttribute(gemm_mma_kernel,
                         cudaFuncAttributeMaxDynamicSharedMemorySize, GEMM_SMEM);
    cudaFuncSetAttribute(flash_mma_kernel,
                         cudaFuncAttributeMaxDynamicSharedMemorySize, FL_SMEM);

    // 0) fp32 -> bf16 hi/lo splits for inputs
    split_bf16_kernel<<<(M_ROWS * EMBED) / 1024, 256>>>(
        (const float4*)x, (ushort4*)xhi, (ushort4*)xlo);
    split_bf16_kernel<<<(QKV_COLS * EMBED) / 1024, 256>>>(
        (const float4*)Win, (ushort4*)w1hi, (ushort4*)w1lo);
    split_bf16_kernel<<<(EMBED * EMBED) / 1024, 256>>>(
        (const float4*)Wout, (ushort4*)w2hi, (ushort4*)w2lo);

    // 1) QKV projection -> bf16 hi/lo qkv (Q pre-scaled by 0.125)
    gemm_mma_kernel<<<dim3(QKV_COLS / 128, M_ROWS / 128), 256, GEMM_SMEM>>>(
        xhi, xlo, w1hi, w1lo, bin, nullptr, qkvhi, qkvlo, QKV_COLS, EMBED);

    // 2) Flash attention on tensor cores -> bf16 hi/lo attn
    flash_mma_kernel<<<dim3(S_LEN / 128, BATCH * HEADS), 256, FL_SMEM>>>(
        qkvhi, qkvlo, ahi, alo);

    // 3) Output projection -> fp32 out
    gemm_mma_kernel<<<dim3(EMBED / 128, M_ROWS / 128), 256, GEMM_SMEM>>>(
        ahi, alo, w2hi, w2lo, bout, out, nullptr, nullptr, EMBED, 0);
}